// round 17
// baseline (speedup 1.0000x reference)
#include <cuda_runtime.h>
#include <cuda_fp16.h>
#include <cstdint>

#define B_    2
#define LQ_   2048
#define LKV_  2048
#define DQ_   1024
#define HID_  1024
#define NH_   16
#define HD_   64
#define EPS_  1e-5f

// ---------------------------------------------------------------------------
// Scratch (device globals; no allocation allowed)
// ---------------------------------------------------------------------------
__device__ uint8_t g_A8[(size_t)B_ * LQ_ * DQ_];        // query e4m3 [M][K]
__device__ uint8_t g_KV8[(size_t)B_ * LKV_ * DQ_];      // kv e4m3 [M][K]
__device__ uint8_t g_Wq8[(size_t)HID_ * DQ_];           // W^T e4m3 [N][K], x16
__device__ uint8_t g_Wk8[(size_t)HID_ * DQ_];
__device__ uint8_t g_Wv8[(size_t)HID_ * DQ_];
__device__ uint8_t g_Wo8[(size_t)DQ_ * HID_];
__device__ __half  g_Qb[(size_t)B_ * NH_ * LQ_ * HD_];  // f16 head layout
__device__ __half  g_Kb[(size_t)B_ * NH_ * LKV_ * HD_];
__device__ __half  g_Vb[(size_t)B_ * NH_ * LKV_ * HD_];
__device__ uint8_t g_ctx8[(size_t)B_ * LQ_ * HID_];     // ctx e4m3, x64
__device__ float   g_o[(size_t)B_ * LQ_ * DQ_];

// ---------------------------------------------------------------------------
// PTX helpers
// ---------------------------------------------------------------------------
static __device__ __forceinline__ uint32_t sptr(const void* p)
{
    return (uint32_t)__cvta_generic_to_shared(p);
}

static __device__ __forceinline__ void ldsm4(uint32_t& r0, uint32_t& r1,
                                             uint32_t& r2, uint32_t& r3,
                                             uint32_t a)
{
    asm volatile("ldmatrix.sync.aligned.m8n8.x4.shared.b16 {%0,%1,%2,%3}, [%4];"
                 : "=r"(r0), "=r"(r1), "=r"(r2), "=r"(r3) : "r"(a));
}

static __device__ __forceinline__ void ldsm4t(uint32_t& r0, uint32_t& r1,
                                              uint32_t& r2, uint32_t& r3,
                                              uint32_t a)
{
    asm volatile("ldmatrix.sync.aligned.m8n8.x4.trans.shared.b16 {%0,%1,%2,%3}, [%4];"
                 : "=r"(r0), "=r"(r1), "=r"(r2), "=r"(r3) : "r"(a));
}

static __device__ __forceinline__ void mma16816h(uint32_t* c, const uint32_t* a,
                                                 uint32_t b0, uint32_t b1)
{
    asm volatile(
        "mma.sync.aligned.m16n8k16.row.col.f16.f16.f16.f16 "
        "{%0,%1}, {%2,%3,%4,%5}, {%6,%7}, {%0,%1};"
        : "+r"(c[0]), "+r"(c[1])
        : "r"(a[0]), "r"(a[1]), "r"(a[2]), "r"(a[3]), "r"(b0), "r"(b1));
}

// fp8 e4m3 mma, k32, f32 accumulate: 4096 MACs/instr (2x the f16 k16 rate if
// it issues at the same per-instruction cadence).
static __device__ __forceinline__ void mma16832f8(float* c, const uint32_t* a,
                                                  uint32_t b0, uint32_t b1)
{
    asm volatile(
        "mma.sync.aligned.m16n8k32.row.col.f32.e4m3.e4m3.f32 "
        "{%0,%1,%2,%3}, {%4,%5,%6,%7}, {%8,%9}, {%0,%1,%2,%3};"
        : "+f"(c[0]), "+f"(c[1]), "+f"(c[2]), "+f"(c[3])
        : "r"(a[0]), "r"(a[1]), "r"(a[2]), "r"(a[3]), "r"(b0), "r"(b1));
}

// Schraudolph fast exp2 on FMA/ALU pipes.
static __device__ __forceinline__ float fex2(float x)
{
    float t = fmaf(x, 8388608.0f, 1064986823.0f);
    return __int_as_float((int)t);
}

static __device__ __forceinline__ uint32_t hf2(float x, float y)
{
    __half2 h = __float22half2_rn(make_float2(x, y));
    return *reinterpret_cast<uint32_t*>(&h);
}

static __device__ __forceinline__ float2 h2f(uint32_t u)
{
    __half2 h = *reinterpret_cast<__half2*>(&u);
    return __half22float2(h);
}

// Pack two floats to e4m3 pair: low byte = lo, high byte = hi.
static __device__ __forceinline__ uint16_t fp8x2(float lo, float hi)
{
    uint16_t r;
    asm("cvt.rn.satfinite.e4m3x2.f32 %0, %1, %2;" : "=h"(r) : "f"(hi), "f"(lo));
    return r;
}

#define CP16(dst, src) \
    asm volatile("cp.async.cg.shared.global [%0], [%1], 16;" \
                 :: "r"(dst), "l"(src))
#define CPCOMMIT() asm volatile("cp.async.commit_group;")
#define CPWAIT0()  asm volatile("cp.async.wait_group 0;" ::: "memory")
#define CPWAIT1()  asm volatile("cp.async.wait_group 1;" ::: "memory")

// ---------------------------------------------------------------------------
// Activations fp32 -> e4m3 (query + kv fused); 8 elems/thread
// ---------------------------------------------------------------------------
#define ACT8B ((B_ * LQ_ * DQ_) / 8)

__global__ __launch_bounds__(256)
void cvt_act8(const float* __restrict__ q, const float* __restrict__ kv,
              uint8_t* dq, uint8_t* dkv)
{
    int i = blockIdx.x * blockDim.x + threadIdx.x;
    const float* src = (i < ACT8B) ? q : kv;
    uint8_t* dst = (i < ACT8B) ? dq : dkv;
    int off = (i < ACT8B) ? i : (i - ACT8B);
    const float4* s = (const float4*)src + (size_t)off * 2;
    float4 a = s[0], b = s[1];
    uint32_t lo = (uint32_t)fp8x2(a.x, a.y) | ((uint32_t)fp8x2(a.z, a.w) << 16);
    uint32_t hi = (uint32_t)fp8x2(b.x, b.y) | ((uint32_t)fp8x2(b.z, b.w) << 16);
    uint2 u; u.x = lo; u.y = hi;
    *((uint2*)dst + off) = u;
}

// ---------------------------------------------------------------------------
// Weights fp32 [K][N] -> e4m3 [N][K], pre-scaled x16 (exact pow2)
// ---------------------------------------------------------------------------
__global__ __launch_bounds__(256)
void cvt_w8t(const float* __restrict__ W, uint8_t* __restrict__ Wt,
             int K, int N)
{
    __shared__ float t[32][33];
    const int k0 = blockIdx.y * 32, n0 = blockIdx.x * 32;
    const int tx = threadIdx.x, ty = threadIdx.y;   // (32, 8)
#pragma unroll
    for (int i = 0; i < 4; i++)
        t[ty + 8 * i][tx] = W[(size_t)(k0 + ty + 8 * i) * N + n0 + tx];
    __syncthreads();
    float v0 = t[ty * 4 + 0][tx] * 16.f;
    float v1 = t[ty * 4 + 1][tx] * 16.f;
    float v2 = t[ty * 4 + 2][tx] * 16.f;
    float v3 = t[ty * 4 + 3][tx] * 16.f;
    uint32_t u = (uint32_t)fp8x2(v0, v1) | ((uint32_t)fp8x2(v2, v3) << 16);
    *(uint32_t*)(Wt + (size_t)(n0 + tx) * K + k0 + ty * 4) = u;
}

// ---------------------------------------------------------------------------
// fp8 GEMM: C = A[M,K] @ (Wt[N,K])^T * wdiv + bias, 128x128 tile, K-step 64,
// 3-stage cp.async, 1 sync/iter. Both fragments via plain ldsm.b16 (byte-pair
// view of fp8 is layout-compatible). 80B smem row stride: conflict-free ldsm.
// ---------------------------------------------------------------------------
#define LD8 80                      // bytes per 64B row incl pad
#define F8_TSZ (128 * LD8)          // one tile (A or B) per stage
#define GEMM8_SMEM (3 * 2 * F8_TSZ) // 61440 B

template<int HEADOUT>
static __device__ __forceinline__ void gemm8_body(
    const uint8_t* __restrict__ A, const uint8_t* __restrict__ Wt,
    const float* __restrict__ bias, void* __restrict__ Cp,
    int M, int N, int K, float wdiv, float scale, uint8_t* dsm)
{
    uint8_t* As = dsm;                    // [3][128*LD8]
    uint8_t* Bs = dsm + 3 * F8_TSZ;

    const int tid = threadIdx.x;
    const int wid = tid >> 5;
    const int lane = tid & 31;
    const int gid = lane >> 2, tg = lane & 3;
    const int m0 = blockIdx.y * 128;
    const int n0 = blockIdx.x * 128;
    const int warp_m = wid >> 2;   // 0..1 -> 64 m rows
    const int warp_n = wid & 3;    // 0..3 -> 32 n cols

    float acc[4][4][4];
#pragma unroll
    for (int i = 0; i < 4; i++)
#pragma unroll
        for (int j = 0; j < 4; j++)
#pragma unroll
            for (int e = 0; e < 4; e++) acc[i][j][e] = 0.f;

    // A fragment addresses: rows lane&15, k-half (lane>>4)*16B
    const uint32_t lmA = (lane & 15) * LD8 + (lane >> 4) * 16;
    // B fragment addresses: rows (lane&7)+((lane>>4)&1)*8, k-half ((lane>>3)&1)*16B
    const uint32_t lmB = ((lane & 7) + ((lane >> 4) & 1) * 8) * LD8
                       + ((lane >> 3) & 1) * 16;

    const int sr = tid >> 1, sc16 = (tid & 1) << 1;   // staging: 2 CP16/row pair

    const int KT = K >> 6;

    auto stage = [&](int s, int k0) {
        uint8_t* as = As + s * F8_TSZ;
        uint8_t* bs = Bs + s * F8_TSZ;
        // 128 rows x 64B each => 512 CP16 per tile; 256 threads: 2 each
        CP16(sptr(as + sr * LD8 + sc16 * 16),
             A + (size_t)(m0 + sr) * K + k0 + sc16 * 16);
        CP16(sptr(as + sr * LD8 + (sc16 + 1) * 16),
             A + (size_t)(m0 + sr) * K + k0 + (sc16 + 1) * 16);
        CP16(sptr(bs + sr * LD8 + sc16 * 16),
             Wt + (size_t)(n0 + sr) * K + k0 + sc16 * 16);
        CP16(sptr(bs + sr * LD8 + (sc16 + 1) * 16),
             Wt + (size_t)(n0 + sr) * K + k0 + (sc16 + 1) * 16);
    };

    stage(0, 0);  CPCOMMIT();
    stage(1, 64); CPCOMMIT();

    int slot = 0;
#pragma unroll 1
    for (int kt = 0; kt < KT; kt++) {
        CPWAIT1();
        __syncthreads();
        if (kt + 2 < KT) {
            int ns = slot + 2; if (ns >= 3) ns -= 3;
            stage(ns, (kt + 2) << 6);
        }
        CPCOMMIT();

        const uint32_t aAddr = sptr(As + slot * F8_TSZ);
        const uint32_t bAddr = sptr(Bs + slot * F8_TSZ);
#pragma unroll
        for (int ks = 0; ks < 2; ks++) {      // two k32 steps per k64 tile
            uint32_t af[4][4];
#pragma unroll
            for (int i = 0; i < 4; i++)
                ldsm4(af[i][0], af[i][1], af[i][2], af[i][3],
                      aAddr + lmA + (warp_m * 64 + i * 16) * LD8 + ks * 32);
            uint32_t bf[4][2];
#pragma unroll
            for (int j2 = 0; j2 < 2; j2++) {
                uint32_t r0, r1, r2, r3;
                ldsm4(r0, r1, r2, r3,
                      bAddr + lmB + (warp_n * 32 + j2 * 16) * LD8 + ks * 32);
                bf[j2 * 2][0] = r0;     bf[j2 * 2][1] = r1;
                bf[j2 * 2 + 1][0] = r2; bf[j2 * 2 + 1][1] = r3;
            }
#pragma unroll
            for (int i = 0; i < 4; i++)
#pragma unroll
                for (int j = 0; j < 4; j++)
                    mma16832f8(acc[i][j], af[i], bf[j][0], bf[j][1]);
        }
        slot++; if (slot >= 3) slot = 0;
    }

#pragma unroll
    for (int i = 0; i < 4; i++) {
        int row = m0 + warp_m * 64 + i * 16 + gid;
#pragma unroll
        for (int j = 0; j < 4; j++) {
            int col = n0 + warp_n * 32 + j * 8 + tg * 2;
            float2 bv = *(const float2*)(bias + col);
            float v0 = (acc[i][j][0] * wdiv + bv.x) * scale;
            float v1 = (acc[i][j][1] * wdiv + bv.y) * scale;
            float v2 = (acc[i][j][2] * wdiv + bv.x) * scale;
            float v3 = (acc[i][j][3] * wdiv + bv.y) * scale;
            if (HEADOUT) {
                int b = row >> 11, l = row & 2047;
                int h = col >> 6, d = col & 63;
                __half* Cb = (__half*)Cp;
                size_t base = (((size_t)b * NH_ + h) * LQ_ + l) * HD_ + d;
                *(uint32_t*)(Cb + base) = hf2(v0, v1);
                *(uint32_t*)(Cb + base + 8 * HD_) = hf2(v2, v3);
            } else {
                float* C = (float*)Cp;
                *(float2*)(C + (size_t)row * N + col) = make_float2(v0, v1);
                *(float2*)(C + (size_t)(row + 8) * N + col) = make_float2(v2, v3);
            }
        }
    }
}

__global__ __launch_bounds__(256, 2)
void gemm_qkv(const uint8_t* Aq, const uint8_t* Akv,
              const uint8_t* Wq, const uint8_t* Wk, const uint8_t* Wv,
              const float* bq, const float* bk, const float* bv,
              __half* Cq, __half* Ck, __half* Cv, float qscale)
{
    extern __shared__ uint8_t dsm8[];
    const int z = blockIdx.z;
    const uint8_t* A = (z == 0) ? Aq : Akv;
    const uint8_t* W = (z == 0) ? Wq : ((z == 1) ? Wk : Wv);
    const float* bias = (z == 0) ? bq : ((z == 1) ? bk : bv);
    __half* C = (z == 0) ? Cq : ((z == 1) ? Ck : Cv);
    float scale = (z == 0) ? qscale : 1.0f;
    gemm8_body<1>(A, W, bias, C, B_ * LQ_, HID_, DQ_, 1.f / 16.f, scale, dsm8);
}

__global__ __launch_bounds__(256, 2)
void gemm_o(const uint8_t* A, const uint8_t* W, const float* bias, float* C)
{
    extern __shared__ uint8_t dsm8[];
    // ctx was stored x64, weights x16 -> divide by 1024
    gemm8_body<0>(A, W, bias, C, B_ * LQ_, DQ_, HID_, 1.f / 1024.f, 1.f, dsm8);
}

// ---------------------------------------------------------------------------
// Flash attention (f16 path, unchanged structure): 4 warps x 32 q rows,
// 3-stage KV pipeline, 4 CTAs/SM, f16-acc MMAs, Schraudolph softmax.
// Epilogue writes ctx as e4m3 scaled x64 for the fp8 O-projection.
// ---------------------------------------------------------------------------
#define LDS_ 72
#define A_TSZ (64 * LDS_)
#define ATTN_SMEM (6 * A_TSZ * 2)

__global__ __launch_bounds__(128, 4)
void attn_mma(const __half* __restrict__ Qg,
              const __half* __restrict__ Kg,
              const __half* __restrict__ Vg,
              uint8_t* __restrict__ ctx)
{
    extern __shared__ __half asm_[];
    __half* Ks = asm_;
    __half* Vs = asm_ + 3 * A_TSZ;

    const int tid = threadIdx.x;
    const int wid = tid >> 5;
    const int lane = tid & 31;
    const int gid = lane >> 2, tg = lane & 3;
    const int q0 = blockIdx.x * 128;
    const int h  = blockIdx.y;
    const int b  = blockIdx.z;

    const size_t baseQ  = (((size_t)b * NH_ + h) * LQ_ + q0) * HD_;
    const size_t baseKV = (((size_t)b * NH_ + h) * LKV_) * HD_;

    const uint32_t lmOff = ((lane & 15) * LDS_ + (lane >> 4) * 8) * 2;

#pragma unroll
    for (int t = 0; t < 8; t++) {
        int idx = tid + t * 128;
        int r = idx >> 3, c8 = (idx & 7) << 3;
        __half* dst = (r < 64) ? (Ks + r * LDS_ + c8)
                               : (Vs + (r - 64) * LDS_ + c8);
        CP16(sptr(dst), Qg + baseQ + (size_t)r * HD_ + c8);
    }
    CPCOMMIT(); CPWAIT0();
    __syncthreads();

    uint32_t qf[2][4][4];
#pragma unroll
    for (int g = 0; g < 2; g++) {
        int qr = wid * 32 + g * 16;
        const __half* qb = (qr < 64) ? Ks : Vs;
        int r = (qr < 64) ? qr : (qr - 64);
#pragma unroll
        for (int ks = 0; ks < 4; ks++)
            ldsm4(qf[g][ks][0], qf[g][ks][1], qf[g][ks][2], qf[g][ks][3],
                  sptr(qb) + lmOff + (r * LDS_ + ks * 16) * 2);
    }
    __syncthreads();

    uint32_t cacc[2][8][2];
#pragma unroll
    for (int g = 0; g < 2; g++)
#pragma unroll
        for (int j = 0; j < 8; j++) { cacc[g][j][0] = 0u; cacc[g][j][1] = 0u; }
    float lsum[4] = {0.f, 0.f, 0.f, 0.f};

    auto stageKV = [&](int s, int kt) {
        const size_t bb = baseKV + (size_t)kt * 64 * HD_;
        __half* ks = Ks + s * A_TSZ;
        __half* vs = Vs + s * A_TSZ;
#pragma unroll
        for (int t = 0; t < 4; t++) {
            int idx = tid + t * 128;
            int r = idx >> 3, c8 = (idx & 7) << 3;
            CP16(sptr(ks + r * LDS_ + c8), Kg + bb + (size_t)r * HD_ + c8);
            CP16(sptr(vs + r * LDS_ + c8), Vg + bb + (size_t)r * HD_ + c8);
        }
    };

    stageKV(0, 0); CPCOMMIT();
    stageKV(1, 1); CPCOMMIT();

    const int KT = LKV_ / 64;
    int slot = 0;
#pragma unroll 1
    for (int kt = 0; kt < KT; kt++) {
        CPWAIT1();
        __syncthreads();
        if (kt + 2 < KT) {
            int ns = slot + 2; if (ns >= 3) ns -= 3;
            stageKV(ns, kt + 2);
        }
        CPCOMMIT();

        const uint32_t ksAddr = sptr(Ks + slot * A_TSZ);
        const uint32_t vsAddr = sptr(Vs + slot * A_TSZ);

#pragma unroll
        for (int jj = 0; jj < 4; jj++) {
            uint32_t pa[2][4];
#pragma unroll
            for (int g = 0; g < 2; g++) {
                uint32_t s0[2] = {0u, 0u};
                uint32_t s1[2] = {0u, 0u};
#pragma unroll
                for (int ks = 0; ks < 4; ks++) {
                    uint32_t r0, r1, r2, r3;
                    ldsm4(r0, r1, r2, r3,
                          ksAddr + lmOff + (jj * 16 * LDS_ + ks * 16) * 2);
                    mma16816h(s0, qf[g][ks], r0, r2);
                    mma16816h(s1, qf[g][ks], r1, r3);
                }
                float2 u0 = h2f(s0[0]);
                float2 u1 = h2f(s0[1]);
                float2 u2 = h2f(s1[0]);
                float2 u3 = h2f(s1[1]);
                float a0 = fex2(u0.x), a1 = fex2(u0.y);
                float a2 = fex2(u1.x), a3 = fex2(u1.y);
                float b0 = fex2(u2.x), b1 = fex2(u2.y);
                float b2 = fex2(u3.x), b3 = fex2(u3.y);
                lsum[2 * g]     += a0 + a1 + b0 + b1;
                lsum[2 * g + 1] += a2 + a3 + b2 + b3;
                pa[g][0] = hf2(a0, a1);
                pa[g][1] = hf2(a2, a3);
                pa[g][2] = hf2(b0, b1);
                pa[g][3] = hf2(b2, b3);
            }
#pragma unroll
            for (int dd = 0; dd < 4; dd++) {
                uint32_t r0, r1, r2, r3;
                ldsm4t(r0, r1, r2, r3,
                       vsAddr + lmOff + (jj * 16 * LDS_ + dd * 16) * 2);
                mma16816h(cacc[0][dd * 2],     pa[0], r0, r1);
                mma16816h(cacc[0][dd * 2 + 1], pa[0], r2, r3);
                mma16816h(cacc[1][dd * 2],     pa[1], r0, r1);
                mma16816h(cacc[1][dd * 2 + 1], pa[1], r2, r3);
            }
        }
        slot++; if (slot >= 3) slot = 0;
    }

#pragma unroll
    for (int u = 0; u < 4; u++) {
        lsum[u] += __shfl_xor_sync(0xffffffffu, lsum[u], 1);
        lsum[u] += __shfl_xor_sync(0xffffffffu, lsum[u], 2);
    }

    // Epilogue: normalize, write e4m3 ctx (x64) [b*l][hid]
#pragma unroll
    for (int g = 0; g < 2; g++) {
        const float inv0 = 64.f / lsum[2 * g];
        const float inv1 = 64.f / lsum[2 * g + 1];
        const int row0 = q0 + wid * 32 + g * 16 + gid;
        const size_t obase = ((size_t)(b * LQ_) + row0) * HID_ + h * HD_;
#pragma unroll
        for (int j = 0; j < 8; j++) {
            int col = j * 8 + tg * 2;
            float2 lo = h2f(cacc[g][j][0]);
            float2 hi = h2f(cacc[g][j][1]);
            *(uint16_t*)(ctx + obase + col) =
                fp8x2(lo.x * inv0, lo.y * inv0);
            *(uint16_t*)(ctx + obase + 8 * HID_ + col) =
                fp8x2(hi.x * inv1, hi.y * inv1);
        }
    }
}

// ---------------------------------------------------------------------------
// LayerNorm(residual + proj): one warp per row
// ---------------------------------------------------------------------------
__global__ __launch_bounds__(256)
void ln_kernel(const float* __restrict__ q, const float* __restrict__ o,
               const float* __restrict__ gamma, const float* __restrict__ beta,
               float* __restrict__ out)
{
    const int row = blockIdx.x * 8 + (threadIdx.x >> 5);
    const int lane = threadIdx.x & 31;
    const size_t base = (size_t)row * 1024;

    float4 x[8];
    float s = 0.f, ss = 0.f;
#pragma unroll
    for (int t = 0; t < 8; t++) {
        int idx = (t * 32 + lane) * 4;
        float4 qa = *(const float4*)(q + base + idx);
        float4 oa = *(const float4*)(o + base + idx);
        x[t].x = qa.x + oa.x; x[t].y = qa.y + oa.y;
        x[t].z = qa.z + oa.z; x[t].w = qa.w + oa.w;
        s  += x[t].x + x[t].y + x[t].z + x[t].w;
        ss += x[t].x * x[t].x + x[t].y * x[t].y
            + x[t].z * x[t].z + x[t].w * x[t].w;
    }
#pragma unroll
    for (int off = 16; off > 0; off >>= 1) {
        s  += __shfl_xor_sync(0xffffffffu, s, off);
        ss += __shfl_xor_sync(0xffffffffu, ss, off);
    }
    float mu = s * (1.f / 1024.f);
    float var = ss * (1.f / 1024.f) - mu * mu;
    float rstd = rsqrtf(var + EPS_);

#pragma unroll
    for (int t = 0; t < 8; t++) {
        int idx = (t * 32 + lane) * 4;
        float4 g  = *(const float4*)(gamma + idx);
        float4 be = *(const float4*)(beta + idx);
        float4 r;
        r.x = (x[t].x - mu) * rstd * g.x + be.x;
        r.y = (x[t].y - mu) * rstd * g.y + be.y;
        r.z = (x[t].z - mu) * rstd * g.z + be.z;
        r.w = (x[t].w - mu) * rstd * g.w + be.w;
        *(float4*)(out + base + idx) = r;
    }
}

// ---------------------------------------------------------------------------
// Launch
// ---------------------------------------------------------------------------
extern "C" void kernel_launch(void* const* d_in, const int* in_sizes, int n_in,
                              void* d_out, int out_size)
{
    const float* query = (const float*)d_in[0];
    const float* kv    = (const float*)d_in[1];
    const float* Wq    = (const float*)d_in[2];
    const float* bq    = (const float*)d_in[3];
    const float* Wk    = (const float*)d_in[4];
    const float* bk    = (const float*)d_in[5];
    const float* Wv    = (const float*)d_in[6];
    const float* bv    = (const float*)d_in[7];
    const float* Wo    = (const float*)d_in[8];
    const float* bo    = (const float*)d_in[9];
    const float* gamma = (const float*)d_in[10];
    const float* beta  = (const float*)d_in[11];
    float* out = (float*)d_out;

    void *pA, *pKV, *pWq, *pWk, *pWv, *pWo, *pQ, *pK, *pV, *pC, *pO;
    cudaGetSymbolAddress(&pA,  g_A8);
    cudaGetSymbolAddress(&pKV, g_KV8);
    cudaGetSymbolAddress(&pWq, g_Wq8);
    cudaGetSymbolAddress(&pWk, g_Wk8);
    cudaGetSymbolAddress(&pWv, g_Wv8);
    cudaGetSymbolAddress(&pWo, g_Wo8);
    cudaGetSymbolAddress(&pQ,  g_Qb);
    cudaGetSymbolAddress(&pK,  g_Kb);
    cudaGetSymbolAddress(&pV,  g_Vb);
    cudaGetSymbolAddress(&pC,  g_ctx8);
    cudaGetSymbolAddress(&pO,  g_o);

    const int M = B_ * LQ_;   // 4096

    cvt_act8<<<(2 * ACT8B) / 256, 256>>>(query, kv,
                                         (uint8_t*)pA, (uint8_t*)pKV);
    dim3 wg(HID_ / 32, DQ_ / 32), wb(32, 8);
    cvt_w8t<<<wg, wb>>>(Wq, (uint8_t*)pWq, DQ_, HID_);
    cvt_w8t<<<wg, wb>>>(Wk, (uint8_t*)pWk, DQ_, HID_);
    cvt_w8t<<<wg, wb>>>(Wv, (uint8_t*)pWv, DQ_, HID_);
    cvt_w8t<<<wg, wb>>>(Wo, (uint8_t*)pWo, HID_, DQ_);

    cudaFuncSetAttribute(gemm_qkv,
                         cudaFuncAttributeMaxDynamicSharedMemorySize, GEMM8_SMEM);
    cudaFuncSetAttribute(gemm_o,
                         cudaFuncAttributeMaxDynamicSharedMemorySize, GEMM8_SMEM);
    cudaFuncSetAttribute(attn_mma,
                         cudaFuncAttributeMaxDynamicSharedMemorySize, ATTN_SMEM);

    const float qscale = 0.125f * 1.4426950408889634f;

    gemm_qkv<<<dim3(HID_ / 128, M / 128, 3), 256, GEMM8_SMEM>>>(
        (const uint8_t*)pA, (const uint8_t*)pKV,
        (const uint8_t*)pWq, (const uint8_t*)pWk, (const uint8_t*)pWv,
        bq, bk, bv,
        (__half*)pQ, (__half*)pK, (__half*)pV, qscale);

    attn_mma<<<dim3(LQ_ / 128, NH_, B_), 128, ATTN_SMEM>>>(
        (const __half*)pQ, (const __half*)pK,
        (const __half*)pV, (uint8_t*)pC);

    gemm_o<<<dim3(DQ_ / 128, M / 128), 256, GEMM8_SMEM>>>(
        (const uint8_t*)pC, (const uint8_t*)pWo, bo, (float*)pO);

    ln_kernel<<<M / 8, 256>>>(query, (const float*)pO, gamma, beta, out);
}